// round 2
// baseline (speedup 1.0000x reference)
#include <cuda_runtime.h>

// FeatureContraction: out[b,c,w,x,v] = sum_i x[b,c,w,x,v,i] * attr[b,c,i]
// x: [16384, 768, 16] f32, attr: [16384, 16] f32, out: [16384, 768] f32.
// Pure HBM stream (~855 MB). R1: 127 us @ 86% DRAM with 16384 tiny CTAs.
// R2: 8 bc-units per CTA (amortize CTA retire bubbles) + streaming cache
//     hints (x read-once, out write-once).

#define BC_TOTAL   16384      // B*C
#define WXV        768        // X*Y*Y = 3*16*16
#define THREADS    256
#define PER_THR    (WXV / THREADS)   // 3
#define BC_PER_BLK 8
#define GRID       (BC_TOTAL / BC_PER_BLK)   // 2048

__global__ __launch_bounds__(THREADS)
void feature_contraction_kernel(const float4* __restrict__ x,
                                const float4* __restrict__ attr,
                                float* __restrict__ out)
{
    const int bc0 = blockIdx.x * BC_PER_BLK;

#pragma unroll 1
    for (int j = 0; j < BC_PER_BLK; j++) {
        const int bc = bc0 + j;

        // attr[bc, 0:16] — uniform address across the warp: broadcast loads,
        // L1/L2 resident (1 MB total), no smem/sync needed.
        const float4* __restrict__ ab = attr + (size_t)bc * 4;
        const float4 a0 = __ldg(ab + 0);
        const float4 a1 = __ldg(ab + 1);
        const float4 a2 = __ldg(ab + 2);
        const float4 a3 = __ldg(ab + 3);

        const float4* __restrict__ xb = x + (size_t)bc * WXV * 4;
        float* __restrict__ ob = out + (size_t)bc * WXV;

        // Front-batch 12 independent 16B streaming loads (MLP=12/thread).
        float4 v[PER_THR][4];
        int    o[PER_THR];

#pragma unroll
        for (int k = 0; k < PER_THR; k++) {
            o[k] = k * THREADS + threadIdx.x;
            const float4* __restrict__ xp = xb + (size_t)o[k] * 4;
            v[k][0] = __ldcs(xp + 0);
            v[k][1] = __ldcs(xp + 1);
            v[k][2] = __ldcs(xp + 2);
            v[k][3] = __ldcs(xp + 3);
        }

#pragma unroll
        for (int k = 0; k < PER_THR; k++) {
            float s;
            s  = v[k][0].x * a0.x;
            s += v[k][0].y * a0.y;
            s += v[k][0].z * a0.z;
            s += v[k][0].w * a0.w;
            s += v[k][1].x * a1.x;
            s += v[k][1].y * a1.y;
            s += v[k][1].z * a1.z;
            s += v[k][1].w * a1.w;
            s += v[k][2].x * a2.x;
            s += v[k][2].y * a2.y;
            s += v[k][2].z * a2.z;
            s += v[k][2].w * a2.w;
            s += v[k][3].x * a3.x;
            s += v[k][3].y * a3.y;
            s += v[k][3].z * a3.z;
            s += v[k][3].w * a3.w;
            __stcs(ob + o[k], s);
        }
    }
}

extern "C" void kernel_launch(void* const* d_in, const int* in_sizes, int n_in,
                              void* d_out, int out_size)
{
    const float4* x    = (const float4*)d_in[0];
    const float4* attr = (const float4*)d_in[1];
    float*        out  = (float*)d_out;

    feature_contraction_kernel<<<GRID, THREADS>>>(x, attr, out);
}

// round 3
// speedup vs baseline: 1.1131x; 1.1131x over previous
#include <cuda_runtime.h>

// FeatureContraction: out[b,c,w,x,v] = sum_i x[b,c,w,x,v,i] * attr[b,c,i]
// x: [16384, 768, 16] f32, attr: [16384, 16] f32, out: [16384, 768] f32.
// Pure HBM stream (~855 MB).
// R1: 1 bc/CTA, 16384 CTAs -> 127.2 us @ 86% DRAM.  (best)
// R2: 8 bc/CTA serial loop  -> 141 us @ 79% DRAM.   (REGRESSION: intra-CTA
//     serialization bubbles; cross-CTA MLP from many tiny CTAs is what feeds
//     the LSU. Reverted.)
// R3: R1 + streaming cache hints (evict-first on read-once x, write-streaming
//     on write-once out). Single-variable change.

#define BC_TOTAL 16384      // B*C
#define WXV      768        // X*Y*Y = 3*16*16
#define THREADS  256
#define PER_THR  (WXV / THREADS)   // 3

__global__ __launch_bounds__(THREADS)
void feature_contraction_kernel(const float4* __restrict__ x,
                                const float4* __restrict__ attr,
                                float* __restrict__ out)
{
    const int bc = blockIdx.x;

    // Stage attr[bc, 0:16] through shared memory, then broadcast to registers.
    __shared__ float4 s_a[4];
    if (threadIdx.x < 4) {
        s_a[threadIdx.x] = attr[(size_t)bc * 4 + threadIdx.x];
    }
    __syncthreads();

    const float4 a0 = s_a[0];
    const float4 a1 = s_a[1];
    const float4 a2 = s_a[2];
    const float4 a3 = s_a[3];

    const float4* __restrict__ xb = x + (size_t)bc * WXV * 4;
    float* __restrict__ ob = out + (size_t)bc * WXV;

    // Front-batch 12 independent streaming LDG.128 (MLP=12/thread).
    float4 v[PER_THR][4];
    int    o[PER_THR];

#pragma unroll
    for (int k = 0; k < PER_THR; k++) {
        o[k] = k * THREADS + threadIdx.x;
        const float4* __restrict__ xp = xb + (size_t)o[k] * 4;
        v[k][0] = __ldcs(xp + 0);
        v[k][1] = __ldcs(xp + 1);
        v[k][2] = __ldcs(xp + 2);
        v[k][3] = __ldcs(xp + 3);
    }

#pragma unroll
    for (int k = 0; k < PER_THR; k++) {
        float s;
        s  = v[k][0].x * a0.x;
        s += v[k][0].y * a0.y;
        s += v[k][0].z * a0.z;
        s += v[k][0].w * a0.w;
        s += v[k][1].x * a1.x;
        s += v[k][1].y * a1.y;
        s += v[k][1].z * a1.z;
        s += v[k][1].w * a1.w;
        s += v[k][2].x * a2.x;
        s += v[k][2].y * a2.y;
        s += v[k][2].z * a2.z;
        s += v[k][2].w * a2.w;
        s += v[k][3].x * a3.x;
        s += v[k][3].y * a3.y;
        s += v[k][3].z * a3.z;
        s += v[k][3].w * a3.w;
        __stcs(ob + o[k], s);
    }
}

extern "C" void kernel_launch(void* const* d_in, const int* in_sizes, int n_in,
                              void* d_out, int out_size)
{
    const float4* x    = (const float4*)d_in[0];
    const float4* attr = (const float4*)d_in[1];
    float*        out  = (float*)d_out;

    feature_contraction_kernel<<<BC_TOTAL, THREADS>>>(x, attr, out);
}

// round 4
// speedup vs baseline: 1.1328x; 1.0177x over previous
#include <cuda_runtime.h>

// FeatureContraction: out[b,c,w,x,v] = sum_i x[b,c,w,x,v,i] * attr[b,c,i]
// x: [16384, 768, 16] f32, attr: [16384, 16] f32, out: [16384, 768] f32.
// Pure HBM stream (~855 MB).
// R1: 1 bc/CTA, float4 loads      -> 127.2 us @ 86% DRAM, L1=71%.
// R2: 8 bc/CTA serial loop        -> 141 us  (REGRESSION, reverted).
// R3: R1 + ldcs/stcs hints        -> 127.0 us (NEUTRAL).
// R4: 256-bit loads (ld.global.v8.f32, sm_100+): halve LDG count and L1
//     wavefront pressure; force true 48-reg front-batched MLP.

#define BC_TOTAL 16384      // B*C
#define WXV      768        // X*Y*Y = 3*16*16
#define THREADS  256
#define PER_THR  (WXV / THREADS)   // 3

__device__ __forceinline__ void ldg256(const float* __restrict__ p,
                                       float4& lo, float4& hi)
{
    asm("ld.global.v8.f32 {%0,%1,%2,%3,%4,%5,%6,%7}, [%8];"
        : "=f"(lo.x), "=f"(lo.y), "=f"(lo.z), "=f"(lo.w),
          "=f"(hi.x), "=f"(hi.y), "=f"(hi.z), "=f"(hi.w)
        : "l"(p));
}

__global__ __launch_bounds__(THREADS)
void feature_contraction_kernel(const float* __restrict__ x,
                                const float4* __restrict__ attr,
                                float* __restrict__ out)
{
    const int bc = blockIdx.x;

    // Stage attr[bc, 0:16] through shared memory, then broadcast to registers.
    __shared__ float4 s_a[4];
    if (threadIdx.x < 4) {
        s_a[threadIdx.x] = attr[(size_t)bc * 4 + threadIdx.x];
    }
    __syncthreads();

    const float4 a0 = s_a[0];
    const float4 a1 = s_a[1];
    const float4 a2 = s_a[2];
    const float4 a3 = s_a[3];

    // x base for this (b,c): WXV output elems * 16 floats each
    const float* __restrict__ xb = x + (size_t)bc * WXV * 16;
    float* __restrict__ ob = out + (size_t)bc * WXV;

    // Front-batch 6 independent 32B-aligned LDG.256 (full MLP, 48 data regs).
    float4 v[PER_THR][4];
    int    o[PER_THR];

#pragma unroll
    for (int k = 0; k < PER_THR; k++) {
        o[k] = k * THREADS + threadIdx.x;
        const float* __restrict__ xp = xb + (size_t)o[k] * 16;
        ldg256(xp,     v[k][0], v[k][1]);
        ldg256(xp + 8, v[k][2], v[k][3]);
    }

#pragma unroll
    for (int k = 0; k < PER_THR; k++) {
        float s;
        s  = v[k][0].x * a0.x;
        s += v[k][0].y * a0.y;
        s += v[k][0].z * a0.z;
        s += v[k][0].w * a0.w;
        s += v[k][1].x * a1.x;
        s += v[k][1].y * a1.y;
        s += v[k][1].z * a1.z;
        s += v[k][1].w * a1.w;
        s += v[k][2].x * a2.x;
        s += v[k][2].y * a2.y;
        s += v[k][2].z * a2.z;
        s += v[k][2].w * a2.w;
        s += v[k][3].x * a3.x;
        s += v[k][3].y * a3.y;
        s += v[k][3].z * a3.z;
        s += v[k][3].w * a3.w;
        out[(size_t)bc * WXV + o[k]] = s;
    }
    (void)ob;
}

extern "C" void kernel_launch(void* const* d_in, const int* in_sizes, int n_in,
                              void* d_out, int out_size)
{
    const float*  x    = (const float*)d_in[0];
    const float4* attr = (const float4*)d_in[1];
    float*        out  = (float*)d_out;

    feature_contraction_kernel<<<BC_TOTAL, THREADS>>>(x, attr, out);
}